// round 3
// baseline (speedup 1.0000x reference)
#include <cuda_runtime.h>
#include <math.h>

#define T_LEN 4096
#define E_DIM 1024
#define H_DIM 512
#define G4H   2048     // 4*H
#define NBLK  64       // blocks per direction in recurrence
#define UPB   8        // hidden units per block (H_DIM / NBLK)
#define TAGS  5
#define START_TAG 3
#define STOP_TAG  4

// ---------------- scratch (device globals; no runtime allocation) -------------
__device__ float g_Gf[(size_t)T_LEN * G4H];          // 32 MB  precomputed W_ih@x + b, forward
__device__ float g_Gb[(size_t)T_LEN * G4H];          // 32 MB  backward (time-reversed input)
__device__ float g_hsf[(size_t)(T_LEN + 1) * H_DIM]; // h trajectory, forward (hsf[0] = h0)
__device__ float g_hsb[(size_t)(T_LEN + 1) * H_DIM]; // h trajectory, backward-scan order
__device__ int   g_cntf[T_LEN];
__device__ int   g_cntb[T_LEN];
__device__ float g_feats[T_LEN * TAGS];

// ---------------- setup: zero counters, seed h0 ------------------------------
__global__ void setup_kernel(const float* __restrict__ h0) {
    int i = blockIdx.x * blockDim.x + threadIdx.x;
    if (i < T_LEN) { g_cntf[i] = 0; g_cntb[i] = 0; }
    if (i < H_DIM) {
        g_hsf[i] = h0[i];
        g_hsb[i] = h0[H_DIM + i];
    }
}

// ---------------- fused gather + gate GEMM -----------------------------------
// G[dir][t][4H] = W_ih[dir] @ embed[sent_dir[t]] + b[dir]
// dir 0: sent[t], dir 1: sent[T-1-t]
#define BM 128
#define BN 64
#define BK 16
__global__ __launch_bounds__(256) void gemm_gates(
    const int* __restrict__ sent, const float* __restrict__ embed,
    const float* __restrict__ Wf, const float* __restrict__ bf,
    const float* __restrict__ Wb, const float* __restrict__ bb)
{
    const int dir = blockIdx.z;
    const float* W    = dir ? Wb : Wf;
    const float* bias = dir ? bb : bf;
    float* G          = dir ? g_Gb : g_Gf;

    __shared__ float As[BK][BM + 1];
    __shared__ float Bs[BK][BN + 1];
    __shared__ int   sRow[BM];

    const int tid = threadIdx.x;
    const int m0 = blockIdx.y * BM;
    const int n0 = blockIdx.x * BN;

    if (tid < BM) {
        int t = m0 + tid;
        sRow[tid] = dir ? sent[T_LEN - 1 - t] : sent[t];
    }
    __syncthreads();

    const int tx = tid & 15;        // n micro index
    const int ty = tid >> 4;        // m micro index
    const int am = tid >> 1, ah = tid & 1;   // A loader: row am, half ah (8 floats each)
    const int bn = tid >> 2, bq = tid & 3;   // B loader: row bn, quarter bq (4 floats)
    const int aIdx = sRow[am];
    const float* arow = embed + (size_t)aIdx * E_DIM;
    const float* brow = W + (size_t)(n0 + bn) * E_DIM;

    float acc[8][4];
#pragma unroll
    for (int i = 0; i < 8; i++)
#pragma unroll
        for (int j = 0; j < 4; j++) acc[i][j] = 0.f;

    for (int kt = 0; kt < E_DIM; kt += BK) {
        float4 a0 = *(const float4*)(arow + kt + ah * 8);
        float4 a1 = *(const float4*)(arow + kt + ah * 8 + 4);
        As[ah * 8 + 0][am] = a0.x; As[ah * 8 + 1][am] = a0.y;
        As[ah * 8 + 2][am] = a0.z; As[ah * 8 + 3][am] = a0.w;
        As[ah * 8 + 4][am] = a1.x; As[ah * 8 + 5][am] = a1.y;
        As[ah * 8 + 6][am] = a1.z; As[ah * 8 + 7][am] = a1.w;

        float4 b0 = *(const float4*)(brow + kt + bq * 4);
        Bs[bq * 4 + 0][bn] = b0.x; Bs[bq * 4 + 1][bn] = b0.y;
        Bs[bq * 4 + 2][bn] = b0.z; Bs[bq * 4 + 3][bn] = b0.w;
        __syncthreads();

#pragma unroll
        for (int k = 0; k < BK; k++) {
            float a[8], b[4];
#pragma unroll
            for (int i = 0; i < 8; i++) a[i] = As[k][ty + 16 * i];
#pragma unroll
            for (int j = 0; j < 4; j++) b[j] = Bs[k][tx + 16 * j];
#pragma unroll
            for (int i = 0; i < 8; i++)
#pragma unroll
                for (int j = 0; j < 4; j++) acc[i][j] = fmaf(a[i], b[j], acc[i][j]);
        }
        __syncthreads();
    }

#pragma unroll
    for (int j = 0; j < 4; j++) {
        int n = n0 + tx + 16 * j;
        float bv = bias[n];
#pragma unroll
        for (int i = 0; i < 8; i++) {
            int m = m0 + ty + 16 * i;
            G[(size_t)m * G4H + n] = acc[i][j] + bv;
        }
    }
}

// ---------------- persistent recurrence: both directions ----------------------
// 128 blocks total: [0,64) forward, [64,128) backward-scan.
// Block owns 8 hidden units -> 32 rows of W_hh held in registers (32 f/thread).
// Cross-block per-step sync via L2 counters (release: STG,fence,atomicAdd;
// acquire: volatile poll, fence, __syncthreads).
__global__ __launch_bounds__(512, 1) void recurrence_kernel(
    const float* __restrict__ Whf, const float* __restrict__ Whb,
    const float* __restrict__ c0)
{
    const int b   = blockIdx.x;
    const int dir = (b >= NBLK) ? 1 : 0;
    const int blk = dir ? (b - NBLK) : b;
    const float* Wh = dir ? Whb : Whf;
    const float* G  = dir ? g_Gb : g_Gf;
    float* hs       = dir ? g_hsb : g_hsf;
    int* cnt        = dir ? g_cntb : g_cntf;

    const int tid = threadIdx.x;
    const int l = tid >> 4;          // local row 0..31
    const int s = tid & 15;          // segment 0..15 (16 threads per row)
    const int j0 = blk * UPB;
    const int gate = l >> 3, unit = l & 7;
    const int row = gate * H_DIM + j0 + unit;

    // W_hh slice in registers: thread covers elems s + 16k, k<32
    float w[32];
    const float* wr = Wh + (size_t)row * H_DIM;
#pragma unroll
    for (int k = 0; k < 32; k++) w[k] = wr[s + 16 * k];

    float c = 0.f;
    if (tid < UPB) c = c0[dir * H_DIM + j0 + tid];

    __shared__ float sh_h[H_DIM];
    __shared__ float sh_dot[32];

    for (int t = 0; t < T_LEN; t++) {
        // prefetch precomputed gate inputs (independent of h -> hides sync latency)
        float gI = 0.f, gF = 0.f, gG = 0.f, gO = 0.f;
        if (tid < UPB) {
            const float* Gp = G + (size_t)t * G4H + j0 + tid;
            gI = Gp[0];
            gF = Gp[H_DIM];
            gG = Gp[2 * H_DIM];
            gO = Gp[3 * H_DIM];
        }

        if (t > 0) {
            if (tid == 0) {
                volatile int* vp = cnt + (t - 1);
                while (*vp < NBLK) { }
                __threadfence();
            }
            __syncthreads();
        }

        // load h_t (512 floats) into smem
        sh_h[tid] = hs[(size_t)t * H_DIM + tid];
        __syncthreads();

        // dot: 32 MACs per thread, conflict-free (16 distinct banks, x2 broadcast)
        float acc = 0.f;
#pragma unroll
        for (int k = 0; k < 32; k++) acc = fmaf(w[k], sh_h[s + 16 * k], acc);
        acc += __shfl_xor_sync(0xffffffffu, acc, 8);
        acc += __shfl_xor_sync(0xffffffffu, acc, 4);
        acc += __shfl_xor_sync(0xffffffffu, acc, 2);
        acc += __shfl_xor_sync(0xffffffffu, acc, 1);
        if (s == 0) sh_dot[l] = acc;
        __syncthreads();

        if (tid < UPB) {
            float vi = gI + sh_dot[tid];
            float vf = gF + sh_dot[8 + tid];
            float vg = gG + sh_dot[16 + tid];
            float vo = gO + sh_dot[24 + tid];
            float ii = 1.f / (1.f + expf(-vi));
            float ff = 1.f / (1.f + expf(-vf));
            float gg = tanhf(vg);
            float oo = 1.f / (1.f + expf(-vo));
            c = ff * c + ii * gg;
            float h = oo * tanhf(c);
            hs[(size_t)(t + 1) * H_DIM + j0 + tid] = h;
        }
        __syncthreads();
        if (tid == 0) {
            __threadfence();
            atomicAdd(cnt + t, 1);
        }
    }
}

// ---------------- output projection: feats[t][tag] ---------------------------
// hf[t] = hsf[t+1];  hb_time[t] = hsb[T - t]   (backward scan reversed)
__global__ void feats_kernel(const float* __restrict__ Wout,
                             const float* __restrict__ bout)
{
    const int t = blockIdx.x;
    const int w = threadIdx.x >> 5;   // tag (5 warps)
    const int lane = threadIdx.x & 31;
    const float* hf = g_hsf + (size_t)(t + 1) * H_DIM;
    const float* hb = g_hsb + (size_t)(T_LEN - t) * H_DIM;
    const float* wr = Wout + w * (2 * H_DIM);

    float sum = 0.f;
#pragma unroll 4
    for (int e = lane; e < H_DIM; e += 32) sum = fmaf(hf[e], wr[e], sum);
#pragma unroll 4
    for (int e = lane; e < H_DIM; e += 32) sum = fmaf(hb[e], wr[H_DIM + e], sum);

    sum += __shfl_xor_sync(0xffffffffu, sum, 16);
    sum += __shfl_xor_sync(0xffffffffu, sum, 8);
    sum += __shfl_xor_sync(0xffffffffu, sum, 4);
    sum += __shfl_xor_sync(0xffffffffu, sum, 2);
    sum += __shfl_xor_sync(0xffffffffu, sum, 1);
    if (lane == 0) g_feats[t * TAGS + w] = sum + bout[w];
}

// ---------------- Viterbi decode + backtrack (single block) ------------------
__global__ void viterbi_kernel(const float* __restrict__ trans,
                               float* __restrict__ out, int out_size)
{
    extern __shared__ float sFeats[];                 // T_LEN*TAGS floats (80 KB)
    __shared__ unsigned char sBp[T_LEN * TAGS];       // backpointers (20 KB)

    const int tid = threadIdx.x;
    for (int i = tid; i < T_LEN * TAGS; i += blockDim.x) sFeats[i] = g_feats[i];
    __syncthreads();

    if (tid < 32) {
        const int lane = tid;
        float tr[TAGS];
#pragma unroll
        for (int p = 0; p < TAGS; p++) tr[p] = 0.f;
        if (lane < TAGS)
#pragma unroll
            for (int p = 0; p < TAGS; p++) tr[p] = trans[lane * TAGS + p];

        // fv lives in lanes 0..4
        float fv = (lane == START_TAG) ? 0.f : -10000.0f;
        if (lane >= TAGS) fv = -1e30f;

        for (int t = 0; t < T_LEN; t++) {
            float f0 = __shfl_sync(0xffffffffu, fv, 0);
            float f1 = __shfl_sync(0xffffffffu, fv, 1);
            float f2 = __shfl_sync(0xffffffffu, fv, 2);
            float f3 = __shfl_sync(0xffffffffu, fv, 3);
            float f4 = __shfl_sync(0xffffffffu, fv, 4);
            float s0 = f0 + tr[0], s1 = f1 + tr[1], s2 = f2 + tr[2];
            float s3 = f3 + tr[3], s4 = f4 + tr[4];
            float best = s0; int bp = 0;
            if (s1 > best) { best = s1; bp = 1; }
            if (s2 > best) { best = s2; bp = 2; }
            if (s3 > best) { best = s3; bp = 3; }
            if (s4 > best) { best = s4; bp = 4; }
            float feat = (lane < TAGS) ? sFeats[t * TAGS + lane] : 0.f;
            if (lane < TAGS) {
                fv = best + feat;
                sBp[t * TAGS + lane] = (unsigned char)bp;
            }
        }

        // terminal scores, argmax (first-max tie rule via strict >)
        float term = (lane < TAGS) ? (fv + trans[STOP_TAG * TAGS + lane]) : -1e30f;
        float t0 = __shfl_sync(0xffffffffu, term, 0);
        float t1 = __shfl_sync(0xffffffffu, term, 1);
        float t2 = __shfl_sync(0xffffffffu, term, 2);
        float t3 = __shfl_sync(0xffffffffu, term, 3);
        float t4 = __shfl_sync(0xffffffffu, term, 4);

        if (lane == 0) {
            float best = t0; int bl = 0;
            if (t1 > best) { best = t1; bl = 1; }
            if (t2 > best) { best = t2; bl = 2; }
            if (t3 > best) { best = t3; bl = 3; }
            if (t4 > best) { best = t4; bl = 4; }

            // layout: [score, path[0..T-1]] if room for T+1, else path only
            int base = (out_size > T_LEN) ? 1 : 0;
            if (base == 1 && out_size >= 1) out[0] = best;

            int y = bl;
            int idx = base + (T_LEN - 1);
            if (idx < out_size) out[idx] = (float)y;
            for (int t = T_LEN - 1; t >= 1; t--) {
                y = sBp[t * TAGS + y];
                idx = base + (t - 1);
                if (idx < out_size) out[idx] = (float)y;
            }
        }
    }
}

// ---------------- launcher ---------------------------------------------------
extern "C" void kernel_launch(void* const* d_in, const int* in_sizes, int n_in,
                              void* d_out, int out_size)
{
    const int*   sentence = (const int*)  d_in[0];
    const float* embed    = (const float*)d_in[1];
    const float* W_ih_f   = (const float*)d_in[2];
    const float* W_hh_f   = (const float*)d_in[3];
    const float* b_f      = (const float*)d_in[4];
    const float* W_ih_b   = (const float*)d_in[5];
    const float* W_hh_b   = (const float*)d_in[6];
    const float* b_b      = (const float*)d_in[7];
    const float* h0       = (const float*)d_in[8];
    const float* c0       = (const float*)d_in[9];
    const float* W_out    = (const float*)d_in[10];
    const float* b_out    = (const float*)d_in[11];
    const float* trans    = (const float*)d_in[12];
    float* out = (float*)d_out;

    setup_kernel<<<16, 256>>>(h0);

    dim3 gg(G4H / BN, T_LEN / BM, 2);   // (32, 32, 2)
    gemm_gates<<<gg, 256>>>(sentence, embed, W_ih_f, b_f, W_ih_b, b_b);

    recurrence_kernel<<<2 * NBLK, 512>>>(W_hh_f, W_hh_b, c0);

    feats_kernel<<<T_LEN, TAGS * 32>>>(W_out, b_out);

    cudaFuncSetAttribute(viterbi_kernel,
                         cudaFuncAttributeMaxDynamicSharedMemorySize,
                         T_LEN * TAGS * sizeof(float));
    viterbi_kernel<<<1, 1024, T_LEN * TAGS * sizeof(float)>>>(trans, out, out_size);
}

// round 4
// speedup vs baseline: 1.1653x; 1.1653x over previous
#include <cuda_runtime.h>
#include <math.h>

#define T_LEN 4096
#define E_DIM 1024
#define H_DIM 512
#define G4H   2048     // 4*H
#define NBLK  64       // blocks per direction in recurrence
#define UPB   8        // hidden units per block (H_DIM / NBLK)
#define TAGS  5
#define START_TAG 3
#define STOP_TAG  4
#define SENT  2.0f     // impossible h value (|h| < 1 strictly)

// ---------------- scratch (device globals; no runtime allocation) -------------
__device__ float g_Gf[(size_t)T_LEN * G4H];          // precomputed W_ih@x + b, forward
__device__ float g_Gb[(size_t)T_LEN * G4H];          // backward (time-reversed input)
__device__ float g_hsf[(size_t)(T_LEN + 1) * H_DIM]; // h trajectory, forward (row 0 = h0)
__device__ float g_hsb[(size_t)(T_LEN + 1) * H_DIM]; // h trajectory, backward-scan order
__device__ float g_feats[T_LEN * TAGS];

// ---------------- setup: sentinel-fill h trajectories, seed h0 ----------------
__global__ void setup_kernel(const float* __restrict__ h0) {
    int i = blockIdx.x * blockDim.x + threadIdx.x;
    int n = T_LEN * H_DIM;                  // rows 1..T per direction
    if (i < n) {
        g_hsf[H_DIM + i] = SENT;
        g_hsb[H_DIM + i] = SENT;
    }
    if (i < H_DIM) {
        g_hsf[i] = h0[i];
        g_hsb[i] = h0[H_DIM + i];
    }
}

// ---------------- fused gather + gate GEMM -----------------------------------
// G[dir][t][4H] = W_ih[dir] @ embed[sent_dir[t]] + b[dir]
// C = A(4096x1024, gathered) * B^T(2048x1024), 128x128x8 tiles, 8x8 micro.
#define BM 128
#define BN 128
#define BK 8
#define LDS_PITCH 132   // padded row stride (floats) -> conflict-free STS, 16B-aligned rows

__global__ __launch_bounds__(256, 2) void gemm_gates(
    const int* __restrict__ sent, const float* __restrict__ embed,
    const float* __restrict__ Wf, const float* __restrict__ bf,
    const float* __restrict__ Wb, const float* __restrict__ bb)
{
    const int dir = blockIdx.z;
    const float* W    = dir ? Wb : Wf;
    const float* bias = dir ? bb : bf;
    float* G          = dir ? g_Gb : g_Gf;

    __shared__ __align__(16) float As[BK][LDS_PITCH];
    __shared__ __align__(16) float Bs[BK][LDS_PITCH];
    __shared__ int sRow[BM];

    const int tid = threadIdx.x;
    const int m0 = blockIdx.y * BM;
    const int n0 = blockIdx.x * BN;

    if (tid < BM) {
        int t = m0 + tid;
        sRow[tid] = dir ? sent[T_LEN - 1 - t] : sent[t];
    }
    __syncthreads();

    // loaders: row = tid>>1 (0..127), seg = tid&1 (which float4 of the 8-k slab)
    const int lrow = tid >> 1;
    const int seg  = tid & 1;
    const float* arow = embed + (size_t)sRow[lrow] * E_DIM + seg * 4;
    const float* brow = W + (size_t)(n0 + lrow) * E_DIM + seg * 4;

    // compute mapping: 16x16 threads, each 8x8 of the 128x128 tile
    const int ty = tid >> 4;   // m group
    const int tx = tid & 15;   // n group

    float acc[8][8];
#pragma unroll
    for (int i = 0; i < 8; i++)
#pragma unroll
        for (int j = 0; j < 8; j++) acc[i][j] = 0.f;

    float4 pa = *(const float4*)(arow);
    float4 pb = *(const float4*)(brow);

    for (int kt = 0; kt < E_DIM; kt += BK) {
        // stage current slab
        const int r0 = seg * 4;
        As[r0 + 0][lrow] = pa.x; As[r0 + 1][lrow] = pa.y;
        As[r0 + 2][lrow] = pa.z; As[r0 + 3][lrow] = pa.w;
        Bs[r0 + 0][lrow] = pb.x; Bs[r0 + 1][lrow] = pb.y;
        Bs[r0 + 2][lrow] = pb.z; Bs[r0 + 3][lrow] = pb.w;
        __syncthreads();

        // prefetch next slab while computing
        if (kt + BK < E_DIM) {
            pa = *(const float4*)(arow + kt + BK);
            pb = *(const float4*)(brow + kt + BK);
        }

#pragma unroll
        for (int k = 0; k < BK; k++) {
            float4 a0 = *(const float4*)&As[k][ty * 8];
            float4 a1 = *(const float4*)&As[k][ty * 8 + 4];
            float4 b0 = *(const float4*)&Bs[k][tx * 8];
            float4 b1 = *(const float4*)&Bs[k][tx * 8 + 4];
            float a[8] = {a0.x, a0.y, a0.z, a0.w, a1.x, a1.y, a1.z, a1.w};
            float b[8] = {b0.x, b0.y, b0.z, b0.w, b1.x, b1.y, b1.z, b1.w};
#pragma unroll
            for (int i = 0; i < 8; i++)
#pragma unroll
                for (int j = 0; j < 8; j++) acc[i][j] = fmaf(a[i], b[j], acc[i][j]);
        }
        __syncthreads();
    }

    // epilogue: add bias, vectorized stores
    float bv[8];
#pragma unroll
    for (int j = 0; j < 8; j++) bv[j] = bias[n0 + tx * 8 + j];

#pragma unroll
    for (int i = 0; i < 8; i++) {
        int m = m0 + ty * 8 + i;
        float* gp = G + (size_t)m * G4H + n0 + tx * 8;
        float4 v0, v1;
        v0.x = acc[i][0] + bv[0]; v0.y = acc[i][1] + bv[1];
        v0.z = acc[i][2] + bv[2]; v0.w = acc[i][3] + bv[3];
        v1.x = acc[i][4] + bv[4]; v1.y = acc[i][5] + bv[5];
        v1.z = acc[i][6] + bv[6]; v1.w = acc[i][7] + bv[7];
        *(float4*)(gp)     = v0;
        *(float4*)(gp + 4) = v1;
    }
}

// ---------------- persistent recurrence: both directions ----------------------
// 128 blocks: [0,64) forward, [64,128) backward-scan. Block owns 8 hidden units
// (32 W_hh rows in registers). Cross-block sync: each thread polls ITS OWN h
// element against the sentinel — one L2 round trip per step, no fences/atomics.
__global__ __launch_bounds__(512, 1) void recurrence_kernel(
    const float* __restrict__ Whf, const float* __restrict__ Whb,
    const float* __restrict__ c0)
{
    const int b   = blockIdx.x;
    const int dir = (b >= NBLK) ? 1 : 0;
    const int blk = dir ? (b - NBLK) : b;
    const float* Wh = dir ? Whb : Whf;
    const float* G  = dir ? g_Gb : g_Gf;
    float* hs       = dir ? g_hsb : g_hsf;

    const int tid = threadIdx.x;
    const int l = tid >> 4;          // local row 0..31
    const int s = tid & 15;          // segment 0..15 (16 threads per row)
    const int j0 = blk * UPB;
    const int gate = l >> 3, unit = l & 7;
    const int row = gate * H_DIM + j0 + unit;

    // W_hh slice: thread covers h-elements s + 16k, k<32
    float w[32];
    const float* wr = Wh + (size_t)row * H_DIM;
#pragma unroll
    for (int k = 0; k < 32; k++) w[k] = wr[s + 16 * k];

    float c = 0.f;
    if (tid < UPB) c = c0[dir * H_DIM + j0 + tid];

    // transposed h staging: sh_h2[s][k] = h[s + 16k], pitch 36 (16B-aligned rows)
    __shared__ __align__(16) float sh_h2[16 * 36];
    __shared__ float sh_dot[32];

    const int ws = tid & 15;         // write coords: h[tid] -> [tid&15][tid>>4]
    const int wk = tid >> 4;

    for (int t = 0; t < T_LEN; t++) {
        // prefetch precomputed gate inputs (independent of h -> in flight during poll)
        float gI = 0.f, gF = 0.f, gG = 0.f, gO = 0.f;
        if (tid < UPB) {
            const float* Gp = G + (size_t)t * G4H + j0 + tid;
            gI = Gp[0];
            gF = Gp[H_DIM];
            gG = Gp[2 * H_DIM];
            gO = Gp[3 * H_DIM];
        }

        // acquire h_t: poll own element (sentinel scheme)
        float hv;
        if (t == 0) {
            hv = hs[tid];
        } else {
            const volatile float* p = hs + (size_t)t * H_DIM + tid;
            hv = *p;
            while (hv == SENT) hv = *p;
        }
        sh_h2[ws * 36 + wk] = hv;
        __syncthreads();

        // dot: 32 MACs per thread via 8 x LDS.128
        float acc0 = 0.f, acc1 = 0.f, acc2 = 0.f, acc3 = 0.f;
        const float* hp = &sh_h2[s * 36];
#pragma unroll
        for (int q = 0; q < 8; q++) {
            float4 h4 = *(const float4*)(hp + 4 * q);
            acc0 = fmaf(w[4 * q + 0], h4.x, acc0);
            acc1 = fmaf(w[4 * q + 1], h4.y, acc1);
            acc2 = fmaf(w[4 * q + 2], h4.z, acc2);
            acc3 = fmaf(w[4 * q + 3], h4.w, acc3);
        }
        float acc = (acc0 + acc1) + (acc2 + acc3);
        acc += __shfl_xor_sync(0xffffffffu, acc, 8);
        acc += __shfl_xor_sync(0xffffffffu, acc, 4);
        acc += __shfl_xor_sync(0xffffffffu, acc, 2);
        acc += __shfl_xor_sync(0xffffffffu, acc, 1);
        if (s == 0) sh_dot[l] = acc;
        __syncthreads();

        if (tid < UPB) {
            float vi = gI + sh_dot[tid];
            float vf = gF + sh_dot[8 + tid];
            float vg = gG + sh_dot[16 + tid];
            float vo = gO + sh_dot[24 + tid];
            // sigmoid via MUFU.TANH: sig(x) = 0.5*tanh(0.5x)+0.5
            float ii = 0.5f * __tanhf(0.5f * vi) + 0.5f;
            float ff = 0.5f * __tanhf(0.5f * vf) + 0.5f;
            float gg = __tanhf(vg);
            float oo = 0.5f * __tanhf(0.5f * vo) + 0.5f;
            c = ff * c + ii * gg;
            float h = oo * __tanhf(c);
            *(volatile float*)(hs + (size_t)(t + 1) * H_DIM + j0 + tid) = h;
        }
        // no third sync needed: sync #2 protects sh_dot reads vs next-iter writes,
        // and next-iter sync #1 protects sh_h2 overwrite vs this-iter dot reads.
    }
}

// ---------------- output projection: feats[t][tag] ---------------------------
// hf[t] = hsf[t+1];  hb_time[t] = hsb[T - t]   (backward scan reversed)
__global__ void feats_kernel(const float* __restrict__ Wout,
                             const float* __restrict__ bout)
{
    const int t = blockIdx.x;
    const int w = threadIdx.x >> 5;   // tag (5 warps)
    const int lane = threadIdx.x & 31;
    const float* hf = g_hsf + (size_t)(t + 1) * H_DIM;
    const float* hb = g_hsb + (size_t)(T_LEN - t) * H_DIM;
    const float* wr = Wout + w * (2 * H_DIM);

    float sum = 0.f;
#pragma unroll 4
    for (int e = lane; e < H_DIM; e += 32) sum = fmaf(hf[e], wr[e], sum);
#pragma unroll 4
    for (int e = lane; e < H_DIM; e += 32) sum = fmaf(hb[e], wr[H_DIM + e], sum);

    sum += __shfl_xor_sync(0xffffffffu, sum, 16);
    sum += __shfl_xor_sync(0xffffffffu, sum, 8);
    sum += __shfl_xor_sync(0xffffffffu, sum, 4);
    sum += __shfl_xor_sync(0xffffffffu, sum, 2);
    sum += __shfl_xor_sync(0xffffffffu, sum, 1);
    if (lane == 0) g_feats[t * TAGS + w] = sum + bout[w];
}

// ---------------- Viterbi decode + backtrack (single block) ------------------
__global__ void viterbi_kernel(const float* __restrict__ trans,
                               float* __restrict__ out, int out_size)
{
    extern __shared__ float sFeats[];                 // T_LEN*TAGS floats (80 KB)
    __shared__ unsigned char sBp[T_LEN * TAGS];       // backpointers (20 KB)

    const int tid = threadIdx.x;
    for (int i = tid; i < T_LEN * TAGS; i += blockDim.x) sFeats[i] = g_feats[i];
    __syncthreads();

    if (tid < 32) {
        const int lane = tid;
        float tr[TAGS];
#pragma unroll
        for (int p = 0; p < TAGS; p++) tr[p] = 0.f;
        if (lane < TAGS)
#pragma unroll
            for (int p = 0; p < TAGS; p++) tr[p] = trans[lane * TAGS + p];

        float fv = (lane == START_TAG) ? 0.f : -10000.0f;
        if (lane >= TAGS) fv = -1e30f;

        for (int t = 0; t < T_LEN; t++) {
            float f0 = __shfl_sync(0xffffffffu, fv, 0);
            float f1 = __shfl_sync(0xffffffffu, fv, 1);
            float f2 = __shfl_sync(0xffffffffu, fv, 2);
            float f3 = __shfl_sync(0xffffffffu, fv, 3);
            float f4 = __shfl_sync(0xffffffffu, fv, 4);
            float s0 = f0 + tr[0], s1 = f1 + tr[1], s2 = f2 + tr[2];
            float s3 = f3 + tr[3], s4 = f4 + tr[4];
            float best = s0; int bp = 0;
            if (s1 > best) { best = s1; bp = 1; }
            if (s2 > best) { best = s2; bp = 2; }
            if (s3 > best) { best = s3; bp = 3; }
            if (s4 > best) { best = s4; bp = 4; }
            float feat = (lane < TAGS) ? sFeats[t * TAGS + lane] : 0.f;
            if (lane < TAGS) {
                fv = best + feat;
                sBp[t * TAGS + lane] = (unsigned char)bp;
            }
        }

        float term = (lane < TAGS) ? (fv + trans[STOP_TAG * TAGS + lane]) : -1e30f;
        float t0 = __shfl_sync(0xffffffffu, term, 0);
        float t1 = __shfl_sync(0xffffffffu, term, 1);
        float t2 = __shfl_sync(0xffffffffu, term, 2);
        float t3 = __shfl_sync(0xffffffffu, term, 3);
        float t4 = __shfl_sync(0xffffffffu, term, 4);

        if (lane == 0) {
            float best = t0; int bl = 0;
            if (t1 > best) { best = t1; bl = 1; }
            if (t2 > best) { best = t2; bl = 2; }
            if (t3 > best) { best = t3; bl = 3; }
            if (t4 > best) { best = t4; bl = 4; }

            int base = (out_size > T_LEN) ? 1 : 0;
            if (base == 1 && out_size >= 1) out[0] = best;

            int y = bl;
            int idx = base + (T_LEN - 1);
            if (idx < out_size) out[idx] = (float)y;
            for (int t = T_LEN - 1; t >= 1; t--) {
                y = sBp[t * TAGS + y];
                idx = base + (t - 1);
                if (idx < out_size) out[idx] = (float)y;
            }
        }
    }
}

// ---------------- launcher ---------------------------------------------------
extern "C" void kernel_launch(void* const* d_in, const int* in_sizes, int n_in,
                              void* d_out, int out_size)
{
    const int*   sentence = (const int*)  d_in[0];
    const float* embed    = (const float*)d_in[1];
    const float* W_ih_f   = (const float*)d_in[2];
    const float* W_hh_f   = (const float*)d_in[3];
    const float* b_f      = (const float*)d_in[4];
    const float* W_ih_b   = (const float*)d_in[5];
    const float* W_hh_b   = (const float*)d_in[6];
    const float* b_b      = (const float*)d_in[7];
    const float* h0       = (const float*)d_in[8];
    const float* c0       = (const float*)d_in[9];
    const float* W_out    = (const float*)d_in[10];
    const float* b_out    = (const float*)d_in[11];
    const float* trans    = (const float*)d_in[12];
    float* out = (float*)d_out;

    // sentinel fill: T_LEN*H_DIM elements per direction
    setup_kernel<<<(T_LEN * H_DIM + 511) / 512, 512>>>(h0);

    dim3 gg(G4H / BN, T_LEN / BM, 2);   // (16, 32, 2)
    gemm_gates<<<gg, 256>>>(sentence, embed, W_ih_f, b_f, W_ih_b, b_b);

    recurrence_kernel<<<2 * NBLK, 512>>>(W_hh_f, W_hh_b, c0);

    feats_kernel<<<T_LEN, TAGS * 32>>>(W_out, b_out);

    cudaFuncSetAttribute(viterbi_kernel,
                         cudaFuncAttributeMaxDynamicSharedMemorySize,
                         T_LEN * TAGS * sizeof(float));
    viterbi_kernel<<<1, 1024, T_LEN * TAGS * sizeof(float)>>>(trans, out, out_size);
}

// round 5
// speedup vs baseline: 1.5817x; 1.3573x over previous
#include <cuda_runtime.h>
#include <math.h>

#define T_LEN 4096
#define E_DIM 1024
#define H_DIM 512
#define G4H   2048     // 4*H
#define RBLK  128      // recurrence blocks (64 per direction), bids 0..127
#define NBLK  64
#define UPB   8        // hidden units per recurrence block
#define TAGS  5
#define START_TAG 3
#define STOP_TAG  4
#define SENT  2.0f     // impossible h value (|h| < 1 strictly)

// ---------------- scratch (device globals; no runtime allocation) -------------
__device__ float g_Gf[(size_t)T_LEN * G4H];          // gates fwd   (NaN = not ready)
__device__ float g_Gb[(size_t)T_LEN * G4H];          // gates bwd-scan
__device__ float g_hsf[(size_t)(T_LEN + 1) * H_DIM]; // h traj fwd (row0 = h0)
__device__ float g_hsb[(size_t)(T_LEN + 1) * H_DIM]; // h traj bwd-scan
__device__ float g_feats[T_LEN * TAGS];

// ---------------- volatile access helpers ------------------------------------
__device__ __forceinline__ float ldvol(const float* p) {
    float v;
    asm volatile("ld.volatile.global.f32 %0, [%1];" : "=f"(v) : "l"(p));
    return v;
}
__device__ __forceinline__ float2 ldvol2(const float* p) {
    float2 v;
    asm volatile("ld.volatile.global.v2.f32 {%0,%1}, [%2];"
                 : "=f"(v.x), "=f"(v.y) : "l"(p));
    return v;
}
__device__ __forceinline__ void stvol(float* p, float v) {
    asm volatile("st.volatile.global.f32 [%0], %1;" :: "l"(p), "f"(v) : "memory");
}

// ---------------- setup: NaN-fill G, sentinel-fill h, seed h0 -----------------
__global__ void setup_kernel(const float* __restrict__ h0) {
    size_t i = (size_t)blockIdx.x * blockDim.x + threadIdx.x;
    const float qn = __int_as_float(0x7FC00000);
    const float4 nan4 = make_float4(qn, qn, qn, qn);
    const float4 s4 = make_float4(SENT, SENT, SENT, SENT);
    size_t nG4 = (size_t)T_LEN * G4H / 4;      // 2,097,152
    if (i < nG4) {
        ((float4*)g_Gf)[i] = nan4;
        ((float4*)g_Gb)[i] = nan4;
    }
    size_t nH4 = (size_t)T_LEN * H_DIM / 4;    // 524,288
    if (i < nH4) {
        ((float4*)(g_hsf + H_DIM))[i] = s4;
        ((float4*)(g_hsb + H_DIM))[i] = s4;
    }
    if (i < H_DIM) {
        g_hsf[i] = h0[i];
        g_hsb[i] = h0[H_DIM + i];
    }
}

// ---------------- fused GEMM + recurrence -------------------------------------
// Blocks [0,128): persistent LSTM recurrence (both directions), poll G via NaN.
// Blocks [128,1152): gate GEMM G[t] = W_ih @ embed[sent[t]] + b, 128x128x8 tiles.
#define BM 128
#define BN 128
#define BK 8
#define LDS_PITCH 132

__global__ __launch_bounds__(256, 2) void fused_kernel(
    const int* __restrict__ sent, const float* __restrict__ embed,
    const float* __restrict__ Wihf, const float* __restrict__ bf,
    const float* __restrict__ Wihb, const float* __restrict__ bb,
    const float* __restrict__ Whf,  const float* __restrict__ Whb,
    const float* __restrict__ c0)
{
    const int tid = threadIdx.x;

    if (blockIdx.x < RBLK) {
        // ================= recurrence path =================
        const int b   = blockIdx.x;
        const int dir = (b >= NBLK) ? 1 : 0;
        const int blk = dir ? (b - NBLK) : b;
        const float* Wh = dir ? Whb : Whf;
        const float* G  = dir ? g_Gb : g_Gf;
        float* hs       = dir ? g_hsb : g_hsf;

        const int l = tid >> 3;          // row 0..31 (gate*8 + unit)
        const int s = tid & 7;           // segment 0..7 (64 h-elems each)
        const int j0 = blk * UPB;
        const int gate = l >> 3, unit = l & 7;
        const int row = gate * H_DIM + j0 + unit;

        // W_hh slice: thread covers h[64s .. 64s+63]
        float w[64];
        {
            const float4* wr = (const float4*)(Wh + (size_t)row * H_DIM + 64 * s);
#pragma unroll
            for (int q = 0; q < 16; q++) {
                float4 v = wr[q];
                w[4 * q + 0] = v.x; w[4 * q + 1] = v.y;
                w[4 * q + 2] = v.z; w[4 * q + 3] = v.w;
            }
        }

        const bool is_cell = (tid >= 32 && tid < 32 + UPB);
        const int  cu = tid - 32;
        float c = is_cell ? c0[dir * H_DIM + j0 + cu] : 0.f;

        __shared__ __align__(16) float sh[8 * 68];   // transposed h staging
        __shared__ float sh_dot[32];
        __shared__ float sh_g[32];

        for (int t = 0; t < T_LEN; t++) {
            // --- poll gate inputs (warp 0): NaN sentinel ---
            if (tid < 32) {
                const float* gp = G + (size_t)t * G4H
                                    + (tid >> 3) * H_DIM + j0 + (tid & 7);
                float v = ldvol(gp);
                while (v != v) v = ldvol(gp);
                sh_g[tid] = v;
            }
            // --- poll h_t (all threads, float2 each): 2.0f sentinel ---
            {
                const float* hp = hs + (size_t)t * H_DIM + 2 * tid;
                float2 hv;
                if (t == 0) {
                    hv = *(const float2*)hp;
                } else {
                    hv = ldvol2(hp);
                    while (hv.x == SENT || hv.y == SENT) hv = ldvol2(hp);
                }
                int i0 = 2 * tid;
                float* sp = sh + (i0 >> 6) * 68 + (i0 & 63);
                sp[0] = hv.x;
                sp[1] = hv.y;
            }
            __syncthreads();   // sync1: sh, sh_g ready

            // cell threads snapshot gates now (sh_g stable sync1 -> next sync1)
            float gI = 0.f, gF = 0.f, gG = 0.f, gO = 0.f;
            if (is_cell) {
                gI = sh_g[cu];
                gF = sh_g[8 + cu];
                gG = sh_g[16 + cu];
                gO = sh_g[24 + cu];
            }

            // --- dot: 64 MACs/thread via 16 LDS.128 (conflict-free, pitch 68) ---
            float a0 = 0.f, a1 = 0.f, a2 = 0.f, a3 = 0.f;
            const float* hp = sh + s * 68;
#pragma unroll
            for (int q = 0; q < 16; q++) {
                float4 h4 = *(const float4*)(hp + 4 * q);
                a0 = fmaf(w[4 * q + 0], h4.x, a0);
                a1 = fmaf(w[4 * q + 1], h4.y, a1);
                a2 = fmaf(w[4 * q + 2], h4.z, a2);
                a3 = fmaf(w[4 * q + 3], h4.w, a3);
            }
            float acc = (a0 + a1) + (a2 + a3);
            acc += __shfl_xor_sync(0xffffffffu, acc, 4);
            acc += __shfl_xor_sync(0xffffffffu, acc, 2);
            acc += __shfl_xor_sync(0xffffffffu, acc, 1);
            if (s == 0) sh_dot[l] = acc;
            __syncthreads();   // sync2: sh_dot ready

            if (is_cell) {
                float vi = gI + sh_dot[cu];
                float vf = gF + sh_dot[8 + cu];
                float vg = gG + sh_dot[16 + cu];
                float vo = gO + sh_dot[24 + cu];
                float ii = 0.5f * __tanhf(0.5f * vi) + 0.5f;
                float ff = 0.5f * __tanhf(0.5f * vf) + 0.5f;
                float gg = __tanhf(vg);
                float oo = 0.5f * __tanhf(0.5f * vo) + 0.5f;
                c = ff * c + ii * gg;
                float h = oo * __tanhf(c);
                stvol(hs + (size_t)(t + 1) * H_DIM + j0 + cu, h);
            }
        }
        return;
    }

    // ================= GEMM path =================
    const int gid = blockIdx.x - RBLK;
    const int bx = gid & 15;           // n tile (16)
    const int by = (gid >> 4) & 31;    // m tile (32)
    const int dir = gid >> 9;          // direction
    const float* W    = dir ? Wihb : Wihf;
    const float* bias = dir ? bb : bf;
    float* G          = dir ? g_Gb : g_Gf;

    __shared__ __align__(16) float As[BK][LDS_PITCH];
    __shared__ __align__(16) float Bs[BK][LDS_PITCH];
    __shared__ int sRow[BM];

    const int m0 = by * BM;
    const int n0 = bx * BN;

    if (tid < BM) {
        int t = m0 + tid;
        sRow[tid] = dir ? sent[T_LEN - 1 - t] : sent[t];
    }
    __syncthreads();

    const int lrow = tid >> 1;
    const int seg  = tid & 1;
    const float* arow = embed + (size_t)sRow[lrow] * E_DIM + seg * 4;
    const float* brow = W + (size_t)(n0 + lrow) * E_DIM + seg * 4;

    const int ty = tid >> 4;
    const int tx = tid & 15;

    float acc[8][8];
#pragma unroll
    for (int i = 0; i < 8; i++)
#pragma unroll
        for (int j = 0; j < 8; j++) acc[i][j] = 0.f;

    float4 pa = *(const float4*)(arow);
    float4 pb = *(const float4*)(brow);

    for (int kt = 0; kt < E_DIM; kt += BK) {
        const int r0 = seg * 4;
        As[r0 + 0][lrow] = pa.x; As[r0 + 1][lrow] = pa.y;
        As[r0 + 2][lrow] = pa.z; As[r0 + 3][lrow] = pa.w;
        Bs[r0 + 0][lrow] = pb.x; Bs[r0 + 1][lrow] = pb.y;
        Bs[r0 + 2][lrow] = pb.z; Bs[r0 + 3][lrow] = pb.w;
        __syncthreads();

        if (kt + BK < E_DIM) {
            pa = *(const float4*)(arow + kt + BK);
            pb = *(const float4*)(brow + kt + BK);
        }

#pragma unroll
        for (int k = 0; k < BK; k++) {
            float4 a0 = *(const float4*)&As[k][ty * 8];
            float4 a1 = *(const float4*)&As[k][ty * 8 + 4];
            float4 b0 = *(const float4*)&Bs[k][tx * 8];
            float4 b1 = *(const float4*)&Bs[k][tx * 8 + 4];
            float a[8] = {a0.x, a0.y, a0.z, a0.w, a1.x, a1.y, a1.z, a1.w};
            float b[8] = {b0.x, b0.y, b0.z, b0.w, b1.x, b1.y, b1.z, b1.w};
#pragma unroll
            for (int i = 0; i < 8; i++)
#pragma unroll
                for (int j = 0; j < 8; j++) acc[i][j] = fmaf(a[i], b[j], acc[i][j]);
        }
        __syncthreads();
    }

    float bv[8];
#pragma unroll
    for (int j = 0; j < 8; j++) bv[j] = bias[n0 + tx * 8 + j];

#pragma unroll
    for (int i = 0; i < 8; i++) {
        int m = m0 + ty * 8 + i;
        float* gp = G + (size_t)m * G4H + n0 + tx * 8;
        float4 v0, v1;
        v0.x = acc[i][0] + bv[0]; v0.y = acc[i][1] + bv[1];
        v0.z = acc[i][2] + bv[2]; v0.w = acc[i][3] + bv[3];
        v1.x = acc[i][4] + bv[4]; v1.y = acc[i][5] + bv[5];
        v1.z = acc[i][6] + bv[6]; v1.w = acc[i][7] + bv[7];
        *(float4*)(gp)     = v0;
        *(float4*)(gp + 4) = v1;
    }
}

// ---------------- output projection: feats[t][tag] ---------------------------
__global__ void feats_kernel(const float* __restrict__ Wout,
                             const float* __restrict__ bout)
{
    const int t = blockIdx.x;
    const int w = threadIdx.x >> 5;
    const int lane = threadIdx.x & 31;
    const float* hf = g_hsf + (size_t)(t + 1) * H_DIM;
    const float* hb = g_hsb + (size_t)(T_LEN - t) * H_DIM;
    const float* wr = Wout + w * (2 * H_DIM);

    float sum = 0.f;
#pragma unroll 4
    for (int e = lane; e < H_DIM; e += 32) sum = fmaf(hf[e], wr[e], sum);
#pragma unroll 4
    for (int e = lane; e < H_DIM; e += 32) sum = fmaf(hb[e], wr[H_DIM + e], sum);

    sum += __shfl_xor_sync(0xffffffffu, sum, 16);
    sum += __shfl_xor_sync(0xffffffffu, sum, 8);
    sum += __shfl_xor_sync(0xffffffffu, sum, 4);
    sum += __shfl_xor_sync(0xffffffffu, sum, 2);
    sum += __shfl_xor_sync(0xffffffffu, sum, 1);
    if (lane == 0) g_feats[t * TAGS + w] = sum + bout[w];
}

// ---------------- Viterbi decode + backtrack (single block) ------------------
__global__ void viterbi_kernel(const float* __restrict__ trans,
                               float* __restrict__ out, int out_size)
{
    extern __shared__ float sFeats[];                 // 80 KB
    __shared__ unsigned char sBp[T_LEN * TAGS];       // 20 KB

    const int tid = threadIdx.x;
    for (int i = tid; i < T_LEN * TAGS; i += blockDim.x) sFeats[i] = g_feats[i];
    __syncthreads();

    if (tid < 32) {
        const int lane = tid;
        float tr[TAGS];
#pragma unroll
        for (int p = 0; p < TAGS; p++) tr[p] = 0.f;
        if (lane < TAGS)
#pragma unroll
            for (int p = 0; p < TAGS; p++) tr[p] = trans[lane * TAGS + p];

        float fv = (lane == START_TAG) ? 0.f : -10000.0f;
        if (lane >= TAGS) fv = -1e30f;

        for (int t = 0; t < T_LEN; t++) {
            float f0 = __shfl_sync(0xffffffffu, fv, 0);
            float f1 = __shfl_sync(0xffffffffu, fv, 1);
            float f2 = __shfl_sync(0xffffffffu, fv, 2);
            float f3 = __shfl_sync(0xffffffffu, fv, 3);
            float f4 = __shfl_sync(0xffffffffu, fv, 4);
            float s0 = f0 + tr[0], s1 = f1 + tr[1], s2 = f2 + tr[2];
            float s3 = f3 + tr[3], s4 = f4 + tr[4];
            float best = s0; int bp = 0;
            if (s1 > best) { best = s1; bp = 1; }
            if (s2 > best) { best = s2; bp = 2; }
            if (s3 > best) { best = s3; bp = 3; }
            if (s4 > best) { best = s4; bp = 4; }
            float feat = (lane < TAGS) ? sFeats[t * TAGS + lane] : 0.f;
            if (lane < TAGS) {
                fv = best + feat;
                sBp[t * TAGS + lane] = (unsigned char)bp;
            }
        }

        float term = (lane < TAGS) ? (fv + trans[STOP_TAG * TAGS + lane]) : -1e30f;
        float t0 = __shfl_sync(0xffffffffu, term, 0);
        float t1 = __shfl_sync(0xffffffffu, term, 1);
        float t2 = __shfl_sync(0xffffffffu, term, 2);
        float t3 = __shfl_sync(0xffffffffu, term, 3);
        float t4 = __shfl_sync(0xffffffffu, term, 4);

        if (lane == 0) {
            float best = t0; int bl = 0;
            if (t1 > best) { best = t1; bl = 1; }
            if (t2 > best) { best = t2; bl = 2; }
            if (t3 > best) { best = t3; bl = 3; }
            if (t4 > best) { best = t4; bl = 4; }

            int base = (out_size > T_LEN) ? 1 : 0;
            if (base == 1 && out_size >= 1) out[0] = best;

            int y = bl;
            int idx = base + (T_LEN - 1);
            if (idx < out_size) out[idx] = (float)y;
            for (int t = T_LEN - 1; t >= 1; t--) {
                y = sBp[t * TAGS + y];
                idx = base + (t - 1);
                if (idx < out_size) out[idx] = (float)y;
            }
        }
    }
}

// ---------------- launcher ---------------------------------------------------
extern "C" void kernel_launch(void* const* d_in, const int* in_sizes, int n_in,
                              void* d_out, int out_size)
{
    const int*   sentence = (const int*)  d_in[0];
    const float* embed    = (const float*)d_in[1];
    const float* W_ih_f   = (const float*)d_in[2];
    const float* W_hh_f   = (const float*)d_in[3];
    const float* b_f      = (const float*)d_in[4];
    const float* W_ih_b   = (const float*)d_in[5];
    const float* W_hh_b   = (const float*)d_in[6];
    const float* b_b      = (const float*)d_in[7];
    const float* h0       = (const float*)d_in[8];
    const float* c0       = (const float*)d_in[9];
    const float* W_out    = (const float*)d_in[10];
    const float* b_out    = (const float*)d_in[11];
    const float* trans    = (const float*)d_in[12];
    float* out = (float*)d_out;

    // cover G NaN-fill: T_LEN*G4H/4 = 2,097,152 float4 stores
    setup_kernel<<<8192, 256>>>(h0);

    // 128 recurrence blocks + 1024 GEMM blocks, one grid, overlapped
    fused_kernel<<<RBLK + 1024, 256>>>(sentence, embed,
                                       W_ih_f, b_f, W_ih_b, b_b,
                                       W_hh_f, W_hh_b, c0);

    feats_kernel<<<T_LEN, TAGS * 32>>>(W_out, b_out);

    cudaFuncSetAttribute(viterbi_kernel,
                         cudaFuncAttributeMaxDynamicSharedMemorySize,
                         T_LEN * TAGS * sizeof(float));
    viterbi_kernel<<<1, 1024, T_LEN * TAGS * sizeof(float)>>>(trans, out, out_size);
}

// round 6
// speedup vs baseline: 1.7742x; 1.1217x over previous
#include <cuda_runtime.h>
#include <math.h>

#define T_LEN 4096
#define E_DIM 1024
#define H_DIM 512
#define G4H   2048     // 4*H
#define RBLK  128      // recurrence blocks (64 per direction), bids 0..127
#define NBLK  64
#define UPB   8        // hidden units per recurrence block (1 per warp)
#define TAGS  5
#define START_TAG 3
#define STOP_TAG  4
#define SENT  2.0f     // impossible h value (|h| < 1 strictly)

// ---------------- scratch (device globals; no runtime allocation) -------------
__device__ float g_Gf[(size_t)T_LEN * G4H];          // gates fwd   (NaN = not ready)
__device__ float g_Gb[(size_t)T_LEN * G4H];          // gates bwd-scan
__device__ float g_hsf[(size_t)(T_LEN + 1) * H_DIM]; // h traj fwd (row0 = h0)
__device__ float g_hsb[(size_t)(T_LEN + 1) * H_DIM]; // h traj bwd-scan
__device__ float g_feats[T_LEN * TAGS];

// ---------------- volatile access helpers ------------------------------------
__device__ __forceinline__ float ldvol(const float* p) {
    float v;
    asm volatile("ld.volatile.global.f32 %0, [%1];" : "=f"(v) : "l"(p));
    return v;
}
__device__ __forceinline__ float2 ldvol2(const float* p) {
    float2 v;
    asm volatile("ld.volatile.global.v2.f32 {%0,%1}, [%2];"
                 : "=f"(v.x), "=f"(v.y) : "l"(p));
    return v;
}
__device__ __forceinline__ void stvol(float* p, float v) {
    asm volatile("st.volatile.global.f32 [%0], %1;" :: "l"(p), "f"(v) : "memory");
}

// ---------------- setup: NaN-fill G, sentinel-fill h, seed h0 -----------------
__global__ void setup_kernel(const float* __restrict__ h0) {
    size_t i = (size_t)blockIdx.x * blockDim.x + threadIdx.x;
    const float qn = __int_as_float(0x7FC00000);
    const float4 nan4 = make_float4(qn, qn, qn, qn);
    const float4 s4 = make_float4(SENT, SENT, SENT, SENT);
    size_t nG4 = (size_t)T_LEN * G4H / 4;      // 2,097,152
    if (i < nG4) {
        ((float4*)g_Gf)[i] = nan4;
        ((float4*)g_Gb)[i] = nan4;
    }
    size_t nH4 = (size_t)T_LEN * H_DIM / 4;    // 524,288
    if (i < nH4) {
        ((float4*)(g_hsf + H_DIM))[i] = s4;
        ((float4*)(g_hsb + H_DIM))[i] = s4;
    }
    if (i < H_DIM) {
        g_hsf[i] = h0[i];
        g_hsb[i] = h0[H_DIM + i];
    }
}

// ---------------- fused GEMM + recurrence -------------------------------------
// Blocks [0,128): persistent LSTM recurrence (both directions), poll G via NaN.
// Blocks [128,1152): gate GEMM, 128x128x8 tiles, TIME-INTERLEAVED dir order.
#define BM 128
#define BN 128
#define BK 8
#define LDS_PITCH 132

__global__ __launch_bounds__(256, 2) void fused_kernel(
    const int* __restrict__ sent, const float* __restrict__ embed,
    const float* __restrict__ Wihf, const float* __restrict__ bf,
    const float* __restrict__ Wihb, const float* __restrict__ bb,
    const float* __restrict__ Whf,  const float* __restrict__ Whb,
    const float* __restrict__ c0)
{
    const int tid = threadIdx.x;

    if (blockIdx.x < RBLK) {
        // ================= recurrence path =================
        const int b   = blockIdx.x;
        const int dir = (b >= NBLK) ? 1 : 0;
        const int blk = dir ? (b - NBLK) : b;
        const float* Wh = dir ? Whb : Whf;
        const float* G  = dir ? g_Gb : g_Gf;
        float* hs       = dir ? g_hsb : g_hsf;

        const int wid  = tid >> 5;       // warp = hidden unit 0..7
        const int lane = tid & 31;
        const int r = lane >> 3;         // gate 0..3
        const int s = lane & 7;          // h segment (64 elems each)
        const int j0 = blk * UPB;
        const int row = r * H_DIM + j0 + wid;

        // W_hh slice: lane covers h[64s .. 64s+63] of its gate row
        float w[64];
        {
            const float4* wr = (const float4*)(Wh + (size_t)row * H_DIM + 64 * s);
#pragma unroll
            for (int q = 0; q < 16; q++) {
                float4 v = wr[q];
                w[4 * q + 0] = v.x; w[4 * q + 1] = v.y;
                w[4 * q + 2] = v.z; w[4 * q + 3] = v.w;
            }
        }

        float c = (lane == 0) ? c0[dir * H_DIM + j0 + wid] : 0.f;

        // double-buffered transposed h staging (pitch 68: conflict-free)
        __shared__ __align__(16) float shbuf[2][8 * 68];

        const float* gbase = G + r * H_DIM + j0 + wid;
        float* hout = hs + j0 + wid;

        for (int t = 0; t < T_LEN; t++) {
            // --- poll G (lane s==0 of each gate row): NaN sentinel ---
            float gv = 0.f;
            if (s == 0) {
                const float* gp = gbase + (size_t)t * G4H;
                gv = ldvol(gp);
                while (gv != gv) gv = ldvol(gp);
            }
            // --- poll h_t (each thread its own float2): 2.0f sentinel ---
            {
                const float* hp = hs + (size_t)t * H_DIM + 2 * tid;
                float2 hv;
                if (t == 0) {
                    hv = *(const float2*)hp;
                } else {
                    hv = ldvol2(hp);
                    while (hv.x == SENT || hv.y == SENT) hv = ldvol2(hp);
                }
                int i0 = 2 * tid;
                float* sp = shbuf[t & 1] + (i0 >> 6) * 68 + (i0 & 63);
                sp[0] = hv.x;
                sp[1] = hv.y;
            }
            __syncthreads();   // only barrier per step (double buffer covers reuse)

            // --- dot: 64 MACs/lane via 16 LDS.128 (8 distinct 16B lines/instr) ---
            float a0 = 0.f, a1 = 0.f, a2 = 0.f, a3 = 0.f;
            const float* hp2 = shbuf[t & 1] + s * 68;
#pragma unroll
            for (int q = 0; q < 16; q++) {
                float4 h4 = *(const float4*)(hp2 + 4 * q);
                a0 = fmaf(w[4 * q + 0], h4.x, a0);
                a1 = fmaf(w[4 * q + 1], h4.y, a1);
                a2 = fmaf(w[4 * q + 2], h4.z, a2);
                a3 = fmaf(w[4 * q + 3], h4.w, a3);
            }
            float acc = (a0 + a1) + (a2 + a3);
            // butterfly within 8-lane gate group
            acc += __shfl_xor_sync(0xffffffffu, acc, 4);
            acc += __shfl_xor_sync(0xffffffffu, acc, 2);
            acc += __shfl_xor_sync(0xffffffffu, acc, 1);
            float v = gv + acc;              // full pre-activation at s==0 lanes
            float vI = __shfl_sync(0xffffffffu, v, 0);
            float vF = __shfl_sync(0xffffffffu, v, 8);
            float vG = __shfl_sync(0xffffffffu, v, 16);
            float vO = __shfl_sync(0xffffffffu, v, 24);

            if (lane == 0) {
                float ii = 0.5f * __tanhf(0.5f * vI) + 0.5f;
                float ff = 0.5f * __tanhf(0.5f * vF) + 0.5f;
                float gg = __tanhf(vG);
                float oo = 0.5f * __tanhf(0.5f * vO) + 0.5f;
                c = ff * c + ii * gg;
                float h = oo * __tanhf(c);
                stvol(hout + (size_t)(t + 1) * H_DIM, h);
            }
        }
        return;
    }

    // ================= GEMM path (time-interleaved dir order) =================
    const int gid = blockIdx.x - RBLK;        // 0..1023
    const int by  = gid >> 5;                 // time tile 0..31 (both dirs together)
    const int dir = (gid >> 4) & 1;
    const int bx  = gid & 15;
    const float* W    = dir ? Wihb : Wihf;
    const float* bias = dir ? bb : bf;
    float* G          = dir ? g_Gb : g_Gf;

    __shared__ __align__(16) float As[BK][LDS_PITCH];
    __shared__ __align__(16) float Bs[BK][LDS_PITCH];
    __shared__ int sRow[BM];

    const int m0 = by * BM;
    const int n0 = bx * BN;

    if (tid < BM) {
        int t = m0 + tid;
        sRow[tid] = dir ? sent[T_LEN - 1 - t] : sent[t];
    }
    __syncthreads();

    const int lrow = tid >> 1;
    const int seg  = tid & 1;
    const float* arow = embed + (size_t)sRow[lrow] * E_DIM + seg * 4;
    const float* brow = W + (size_t)(n0 + lrow) * E_DIM + seg * 4;

    const int ty = tid >> 4;
    const int tx = tid & 15;

    float acc[8][8];
#pragma unroll
    for (int i = 0; i < 8; i++)
#pragma unroll
        for (int j = 0; j < 8; j++) acc[i][j] = 0.f;

    float4 pa = *(const float4*)(arow);
    float4 pb = *(const float4*)(brow);

    for (int kt = 0; kt < E_DIM; kt += BK) {
        const int r0 = seg * 4;
        As[r0 + 0][lrow] = pa.x; As[r0 + 1][lrow] = pa.y;
        As[r0 + 2][lrow] = pa.z; As[r0 + 3][lrow] = pa.w;
        Bs[r0 + 0][lrow] = pb.x; Bs[r0 + 1][lrow] = pb.y;
        Bs[r0 + 2][lrow] = pb.z; Bs[r0 + 3][lrow] = pb.w;
        __syncthreads();

        if (kt + BK < E_DIM) {
            pa = *(const float4*)(arow + kt + BK);
            pb = *(const float4*)(brow + kt + BK);
        }

#pragma unroll
        for (int k = 0; k < BK; k++) {
            float4 a0 = *(const float4*)&As[k][ty * 8];
            float4 a1 = *(const float4*)&As[k][ty * 8 + 4];
            float4 b0 = *(const float4*)&Bs[k][tx * 8];
            float4 b1 = *(const float4*)&Bs[k][tx * 8 + 4];
            float a[8] = {a0.x, a0.y, a0.z, a0.w, a1.x, a1.y, a1.z, a1.w};
            float b[8] = {b0.x, b0.y, b0.z, b0.w, b1.x, b1.y, b1.z, b1.w};
#pragma unroll
            for (int i = 0; i < 8; i++)
#pragma unroll
                for (int j = 0; j < 8; j++) acc[i][j] = fmaf(a[i], b[j], acc[i][j]);
        }
        __syncthreads();
    }

    float bv[8];
#pragma unroll
    for (int j = 0; j < 8; j++) bv[j] = bias[n0 + tx * 8 + j];

#pragma unroll
    for (int i = 0; i < 8; i++) {
        int m = m0 + ty * 8 + i;
        float* gp = G + (size_t)m * G4H + n0 + tx * 8;
        float4 v0, v1;
        v0.x = acc[i][0] + bv[0]; v0.y = acc[i][1] + bv[1];
        v0.z = acc[i][2] + bv[2]; v0.w = acc[i][3] + bv[3];
        v1.x = acc[i][4] + bv[4]; v1.y = acc[i][5] + bv[5];
        v1.z = acc[i][6] + bv[6]; v1.w = acc[i][7] + bv[7];
        *(float4*)(gp)     = v0;
        *(float4*)(gp + 4) = v1;
    }
}

// ---------------- output projection: feats[t][tag] ---------------------------
__global__ void feats_kernel(const float* __restrict__ Wout,
                             const float* __restrict__ bout)
{
    const int t = blockIdx.x;
    const int w = threadIdx.x >> 5;
    const int lane = threadIdx.x & 31;
    const float* hf = g_hsf + (size_t)(t + 1) * H_DIM;
    const float* hb = g_hsb + (size_t)(T_LEN - t) * H_DIM;
    const float* wr = Wout + w * (2 * H_DIM);

    float sum = 0.f;
#pragma unroll 4
    for (int e = lane; e < H_DIM; e += 32) sum = fmaf(hf[e], wr[e], sum);
#pragma unroll 4
    for (int e = lane; e < H_DIM; e += 32) sum = fmaf(hb[e], wr[H_DIM + e], sum);

    sum += __shfl_xor_sync(0xffffffffu, sum, 16);
    sum += __shfl_xor_sync(0xffffffffu, sum, 8);
    sum += __shfl_xor_sync(0xffffffffu, sum, 4);
    sum += __shfl_xor_sync(0xffffffffu, sum, 2);
    sum += __shfl_xor_sync(0xffffffffu, sum, 1);
    if (lane == 0) g_feats[t * TAGS + w] = sum + bout[w];
}

// ---------------- Viterbi decode + backtrack (single block, branchless) ------
__global__ void viterbi_kernel(const float* __restrict__ trans,
                               float* __restrict__ out, int out_size)
{
    extern __shared__ float sFeats[];                 // 80 KB
    __shared__ unsigned char sBp[T_LEN * TAGS];       // 20 KB

    const int tid = threadIdx.x;
    for (int i = tid; i < T_LEN * TAGS; i += blockDim.x) sFeats[i] = g_feats[i];
    __syncthreads();

    if (tid < 32) {
        const int lane = tid;
        float tr[TAGS];
#pragma unroll
        for (int p = 0; p < TAGS; p++) tr[p] = 0.f;
        if (lane < TAGS)
#pragma unroll
            for (int p = 0; p < TAGS; p++) tr[p] = trans[lane * TAGS + p];

        float fv = (lane == START_TAG) ? 0.f : -10000.0f;
        if (lane >= TAGS) fv = -1e30f;

        for (int t = 0; t < T_LEN; t++) {
            float f0 = __shfl_sync(0xffffffffu, fv, 0);
            float f1 = __shfl_sync(0xffffffffu, fv, 1);
            float f2 = __shfl_sync(0xffffffffu, fv, 2);
            float f3 = __shfl_sync(0xffffffffu, fv, 3);
            float f4 = __shfl_sync(0xffffffffu, fv, 4);
            float s0 = f0 + tr[0], s1 = f1 + tr[1], s2 = f2 + tr[2];
            float s3 = f3 + tr[3], s4 = f4 + tr[4];
            // branchless first-max tournament (FMNMX + SEL, no BSSY)
            float m01 = fmaxf(s0, s1); int b01 = (s1 > s0) ? 1 : 0;
            float m23 = fmaxf(s2, s3); int b23 = (s3 > s2) ? 3 : 2;
            float m03 = fmaxf(m01, m23); int b03 = (m23 > m01) ? b23 : b01;
            float best = fmaxf(m03, s4); int bp = (s4 > m03) ? 4 : b03;
            float feat = (lane < TAGS) ? sFeats[t * TAGS + lane] : 0.f;
            fv = (lane < TAGS) ? (best + feat) : fv;
            sBp[t * TAGS + (lane < TAGS ? lane : 0)] =
                (lane < TAGS) ? (unsigned char)bp : sBp[t * TAGS];
        }

        float term = (lane < TAGS) ? (fv + trans[STOP_TAG * TAGS + lane]) : -1e30f;
        float t0 = __shfl_sync(0xffffffffu, term, 0);
        float t1 = __shfl_sync(0xffffffffu, term, 1);
        float t2 = __shfl_sync(0xffffffffu, term, 2);
        float t3 = __shfl_sync(0xffffffffu, term, 3);
        float t4 = __shfl_sync(0xffffffffu, term, 4);

        if (lane == 0) {
            float best = t0; int bl = 0;
            if (t1 > best) { best = t1; bl = 1; }
            if (t2 > best) { best = t2; bl = 2; }
            if (t3 > best) { best = t3; bl = 3; }
            if (t4 > best) { best = t4; bl = 4; }

            int base = (out_size > T_LEN) ? 1 : 0;
            if (base == 1 && out_size >= 1) out[0] = best;

            int y = bl;
            int idx = base + (T_LEN - 1);
            if (idx < out_size) out[idx] = (float)y;
            for (int t = T_LEN - 1; t >= 1; t--) {
                y = sBp[t * TAGS + y];
                idx = base + (t - 1);
                if (idx < out_size) out[idx] = (float)y;
            }
        }
    }
}

// ---------------- launcher ---------------------------------------------------
extern "C" void kernel_launch(void* const* d_in, const int* in_sizes, int n_in,
                              void* d_out, int out_size)
{
    const int*   sentence = (const int*)  d_in[0];
    const float* embed    = (const float*)d_in[1];
    const float* W_ih_f   = (const float*)d_in[2];
    const float* W_hh_f   = (const float*)d_in[3];
    const float* b_f      = (const float*)d_in[4];
    const float* W_ih_b   = (const float*)d_in[5];
    const float* W_hh_b   = (const float*)d_in[6];
    const float* b_b      = (const float*)d_in[7];
    const float* h0       = (const float*)d_in[8];
    const float* c0       = (const float*)d_in[9];
    const float* W_out    = (const float*)d_in[10];
    const float* b_out    = (const float*)d_in[11];
    const float* trans    = (const float*)d_in[12];
    float* out = (float*)d_out;

    setup_kernel<<<8192, 256>>>(h0);

    fused_kernel<<<RBLK + 1024, 256>>>(sentence, embed,
                                       W_ih_f, b_f, W_ih_b, b_b,
                                       W_hh_f, W_hh_b, c0);

    feats_kernel<<<T_LEN, TAGS * 32>>>(W_out, b_out);

    cudaFuncSetAttribute(viterbi_kernel,
                         cudaFuncAttributeMaxDynamicSharedMemorySize,
                         T_LEN * TAGS * sizeof(float));
    viterbi_kernel<<<1, 1024, T_LEN * TAGS * sizeof(float)>>>(trans, out, out_size);
}

// round 7
// speedup vs baseline: 1.7975x; 1.0131x over previous
#include <cuda_runtime.h>
#include <math.h>

#define T_LEN 4096
#define E_DIM 1024
#define H_DIM 512
#define G4H   2048     // 4*H
#define RBLK  128      // recurrence blocks (64 per direction), bids 0..127
#define NBLK  64
#define UPB   8        // hidden units per recurrence block (1 per warp)
#define TAGS  5
#define START_TAG 3
#define STOP_TAG  4
#define SENT  2.0f     // impossible h value (|h| < 1 strictly)

// ---------------- scratch (device globals; no runtime allocation) -------------
__device__ float g_Gf[(size_t)T_LEN * G4H];          // gates fwd   (NaN = not ready)
__device__ float g_Gb[(size_t)T_LEN * G4H];          // gates bwd-scan
__device__ float g_hsf[(size_t)(T_LEN + 1) * H_DIM]; // h traj fwd (row0 = h0)
__device__ float g_hsb[(size_t)(T_LEN + 1) * H_DIM]; // h traj bwd-scan
__device__ float g_feats[T_LEN * TAGS];

// ---------------- volatile access helpers ------------------------------------
__device__ __forceinline__ float ldvol(const float* p) {
    float v;
    asm volatile("ld.volatile.global.f32 %0, [%1];" : "=f"(v) : "l"(p));
    return v;
}
__device__ __forceinline__ float2 ldvol2(const float* p) {
    float2 v;
    asm volatile("ld.volatile.global.v2.f32 {%0,%1}, [%2];"
                 : "=f"(v.x), "=f"(v.y) : "l"(p));
    return v;
}
__device__ __forceinline__ void stvol(float* p, float v) {
    asm volatile("st.volatile.global.f32 [%0], %1;" :: "l"(p), "f"(v) : "memory");
}

// ---------------- setup: NaN-fill G, sentinel-fill h, seed h0 -----------------
__global__ void setup_kernel(const float* __restrict__ h0) {
    size_t i = (size_t)blockIdx.x * blockDim.x + threadIdx.x;
    const float qn = __int_as_float(0x7FC00000);
    const float4 nan4 = make_float4(qn, qn, qn, qn);
    const float4 s4 = make_float4(SENT, SENT, SENT, SENT);
    size_t nG4 = (size_t)T_LEN * G4H / 4;      // 2,097,152
    if (i < nG4) {
        ((float4*)g_Gf)[i] = nan4;
        ((float4*)g_Gb)[i] = nan4;
    }
    size_t nH4 = (size_t)T_LEN * H_DIM / 4;    // 524,288
    if (i < nH4) {
        ((float4*)(g_hsf + H_DIM))[i] = s4;
        ((float4*)(g_hsb + H_DIM))[i] = s4;
    }
    if (i < H_DIM) {
        g_hsf[i] = h0[i];
        g_hsb[i] = h0[H_DIM + i];
    }
}

// ---------------- fused GEMM + recurrence -------------------------------------
// Blocks [0,128): persistent LSTM recurrence, G consumed via NaN-sentinel with a
// one-step software prefetch pipeline (hides the cold-DRAM latency of G).
// Blocks [128,1152): gate GEMM, 128x128x8 tiles, time-interleaved dir order.
#define BM 128
#define BN 128
#define BK 8
#define LDS_PITCH 132

__global__ __launch_bounds__(256, 2) void fused_kernel(
    const int* __restrict__ sent, const float* __restrict__ embed,
    const float* __restrict__ Wihf, const float* __restrict__ bf,
    const float* __restrict__ Wihb, const float* __restrict__ bb,
    const float* __restrict__ Whf,  const float* __restrict__ Whb,
    const float* __restrict__ c0)
{
    const int tid = threadIdx.x;

    if (blockIdx.x < RBLK) {
        // ================= recurrence path =================
        const int b   = blockIdx.x;
        const int dir = (b >= NBLK) ? 1 : 0;
        const int blk = dir ? (b - NBLK) : b;
        const float* Wh = dir ? Whb : Whf;
        const float* G  = dir ? g_Gb : g_Gf;
        float* hs       = dir ? g_hsb : g_hsf;

        const int wid  = tid >> 5;       // warp = hidden unit 0..7
        const int lane = tid & 31;
        const int r = lane >> 3;         // gate 0..3
        const int s = lane & 7;          // h segment (64 elems each)
        const int j0 = blk * UPB;
        const int row = r * H_DIM + j0 + wid;

        // W_hh slice: lane covers h[64s .. 64s+63] of its gate row
        float w[64];
        {
            const float4* wr = (const float4*)(Wh + (size_t)row * H_DIM + 64 * s);
#pragma unroll
            for (int q = 0; q < 16; q++) {
                float4 v = wr[q];
                w[4 * q + 0] = v.x; w[4 * q + 1] = v.y;
                w[4 * q + 2] = v.z; w[4 * q + 3] = v.w;
            }
        }

        float c = (lane == 0) ? c0[dir * H_DIM + j0 + wid] : 0.f;

        // double-buffered transposed h staging (pitch 68: conflict-free)
        __shared__ __align__(16) float shbuf[2][8 * 68];

        const float* gbase = G + r * H_DIM + j0 + wid;
        float* hout = hs + j0 + wid;

        // prefetch G[0]
        float gv = 0.f;
        if (s == 0) gv = ldvol(gbase);

        for (int t = 0; t < T_LEN; t++) {
            // --- issue prefetch of G[t+1] immediately (latency hidden by step) ---
            float gnext = 0.f;
            if (s == 0 && t + 1 < T_LEN)
                gnext = ldvol(gbase + (size_t)(t + 1) * G4H);

            // --- poll h_t (each thread its own float2): 2.0f sentinel ---
            {
                const float* hp = hs + (size_t)t * H_DIM + 2 * tid;
                float2 hv;
                if (t == 0) {
                    hv = *(const float2*)hp;
                } else {
                    hv = ldvol2(hp);
                    while (hv.x == SENT || hv.y == SENT) hv = ldvol2(hp);
                }
                int i0 = 2 * tid;
                float* sp = shbuf[t & 1] + (i0 >> 6) * 68 + (i0 & 63);
                sp[0] = hv.x;
                sp[1] = hv.y;
            }
            __syncthreads();   // only barrier per step

            // --- dot: 64 MACs/lane via 16 LDS.128 (4-way broadcast across gates) ---
            float a0 = 0.f, a1 = 0.f, a2 = 0.f, a3 = 0.f;
            const float* hp2 = shbuf[t & 1] + s * 68;
#pragma unroll
            for (int q = 0; q < 16; q++) {
                float4 h4 = *(const float4*)(hp2 + 4 * q);
                a0 = fmaf(w[4 * q + 0], h4.x, a0);
                a1 = fmaf(w[4 * q + 1], h4.y, a1);
                a2 = fmaf(w[4 * q + 2], h4.z, a2);
                a3 = fmaf(w[4 * q + 3], h4.w, a3);
            }
            float acc = (a0 + a1) + (a2 + a3);
            acc += __shfl_xor_sync(0xffffffffu, acc, 4);
            acc += __shfl_xor_sync(0xffffffffu, acc, 2);
            acc += __shfl_xor_sync(0xffffffffu, acc, 1);

            // --- resolve prefetched gate value (NaN re-poll is the rare path) ---
            if (s == 0) {
                while (gv != gv) gv = ldvol(gbase + (size_t)t * G4H);
            }
            float v = gv + acc;            // full pre-activation at s==0 lanes

            // activation in parallel at lanes 0,8,16,24 (single MUFU, branchless)
            float xin = (r == 2) ? v : (0.5f * v);
            float th  = __tanhf(xin);
            float act = (r == 2) ? th : (0.5f * th + 0.5f);

            float ff = __shfl_sync(0xffffffffu, act, 8);
            float gg = __shfl_sync(0xffffffffu, act, 16);
            float oo = __shfl_sync(0xffffffffu, act, 24);

            if (lane == 0) {
                c = ff * c + act * gg;      // act(lane0) = input gate
                float h = oo * __tanhf(c);
                stvol(hout + (size_t)(t + 1) * H_DIM, h);
            }
            gv = gnext;
        }
        return;
    }

    // ================= GEMM path (time-interleaved dir order) =================
    const int gid = blockIdx.x - RBLK;        // 0..1023
    const int by  = gid >> 5;                 // time tile 0..31 (both dirs together)
    const int dir = (gid >> 4) & 1;
    const int bx  = gid & 15;
    const float* W    = dir ? Wihb : Wihf;
    const float* bias = dir ? bb : bf;
    float* G          = dir ? g_Gb : g_Gf;

    __shared__ __align__(16) float As[BK][LDS_PITCH];
    __shared__ __align__(16) float Bs[BK][LDS_PITCH];
    __shared__ int sRow[BM];

    const int m0 = by * BM;
    const int n0 = bx * BN;

    if (tid < BM) {
        int t = m0 + tid;
        sRow[tid] = dir ? sent[T_LEN - 1 - t] : sent[t];
    }
    __syncthreads();

    const int lrow = tid >> 1;
    const int seg  = tid & 1;
    const float* arow = embed + (size_t)sRow[lrow] * E_DIM + seg * 4;
    const float* brow = W + (size_t)(n0 + lrow) * E_DIM + seg * 4;

    const int ty = tid >> 4;
    const int tx = tid & 15;

    float acc[8][8];
#pragma unroll
    for (int i = 0; i < 8; i++)
#pragma unroll
        for (int j = 0; j < 8; j++) acc[i][j] = 0.f;

    float4 pa = *(const float4*)(arow);
    float4 pb = *(const float4*)(brow);

    for (int kt = 0; kt < E_DIM; kt += BK) {
        const int r0 = seg * 4;
        As[r0 + 0][lrow] = pa.x; As[r0 + 1][lrow] = pa.y;
        As[r0 + 2][lrow] = pa.z; As[r0 + 3][lrow] = pa.w;
        Bs[r0 + 0][lrow] = pb.x; Bs[r0 + 1][lrow] = pb.y;
        Bs[r0 + 2][lrow] = pb.z; Bs[r0 + 3][lrow] = pb.w;
        __syncthreads();

        if (kt + BK < E_DIM) {
            pa = *(const float4*)(arow + kt + BK);
            pb = *(const float4*)(brow + kt + BK);
        }

#pragma unroll
        for (int k = 0; k < BK; k++) {
            float4 a0 = *(const float4*)&As[k][ty * 8];
            float4 a1 = *(const float4*)&As[k][ty * 8 + 4];
            float4 b0 = *(const float4*)&Bs[k][tx * 8];
            float4 b1 = *(const float4*)&Bs[k][tx * 8 + 4];
            float a[8] = {a0.x, a0.y, a0.z, a0.w, a1.x, a1.y, a1.z, a1.w};
            float b[8] = {b0.x, b0.y, b0.z, b0.w, b1.x, b1.y, b1.z, b1.w};
#pragma unroll
            for (int i = 0; i < 8; i++)
#pragma unroll
                for (int j = 0; j < 8; j++) acc[i][j] = fmaf(a[i], b[j], acc[i][j]);
        }
        __syncthreads();
    }

    float bv[8];
#pragma unroll
    for (int j = 0; j < 8; j++) bv[j] = bias[n0 + tx * 8 + j];

#pragma unroll
    for (int i = 0; i < 8; i++) {
        int m = m0 + ty * 8 + i;
        float* gp = G + (size_t)m * G4H + n0 + tx * 8;
        float4 v0, v1;
        v0.x = acc[i][0] + bv[0]; v0.y = acc[i][1] + bv[1];
        v0.z = acc[i][2] + bv[2]; v0.w = acc[i][3] + bv[3];
        v1.x = acc[i][4] + bv[4]; v1.y = acc[i][5] + bv[5];
        v1.z = acc[i][6] + bv[6]; v1.w = acc[i][7] + bv[7];
        *(float4*)(gp)     = v0;
        *(float4*)(gp + 4) = v1;
    }
}

// ---------------- output projection: feats[t][tag] ---------------------------
__global__ void feats_kernel(const float* __restrict__ Wout,
                             const float* __restrict__ bout)
{
    const int t = blockIdx.x;
    const int w = threadIdx.x >> 5;
    const int lane = threadIdx.x & 31;
    const float* hf = g_hsf + (size_t)(t + 1) * H_DIM;
    const float* hb = g_hsb + (size_t)(T_LEN - t) * H_DIM;
    const float* wr = Wout + w * (2 * H_DIM);

    float sum = 0.f;
#pragma unroll 4
    for (int e = lane; e < H_DIM; e += 32) sum = fmaf(hf[e], wr[e], sum);
#pragma unroll 4
    for (int e = lane; e < H_DIM; e += 32) sum = fmaf(hb[e], wr[H_DIM + e], sum);

    sum += __shfl_xor_sync(0xffffffffu, sum, 16);
    sum += __shfl_xor_sync(0xffffffffu, sum, 8);
    sum += __shfl_xor_sync(0xffffffffu, sum, 4);
    sum += __shfl_xor_sync(0xffffffffu, sum, 2);
    sum += __shfl_xor_sync(0xffffffffu, sum, 1);
    if (lane == 0) g_feats[t * TAGS + w] = sum + bout[w];
}

// ---------------- Viterbi decode + backtrack (single block) ------------------
// Lanes 0..4 each own next-tag n; shfl broadcast of fv; feat prefetched 1 ahead.
__global__ void viterbi_kernel(const float* __restrict__ trans,
                               float* __restrict__ out, int out_size)
{
    extern __shared__ float sFeats[];                 // 80 KB
    __shared__ unsigned char sBp[T_LEN * TAGS];       // 20 KB

    const int tid = threadIdx.x;
    for (int i = tid; i < T_LEN * TAGS; i += blockDim.x) sFeats[i] = g_feats[i];
    __syncthreads();

    if (tid < 32) {
        const int lane = tid;
        float tr[TAGS];
#pragma unroll
        for (int p = 0; p < TAGS; p++) tr[p] = 0.f;
        if (lane < TAGS)
#pragma unroll
            for (int p = 0; p < TAGS; p++) tr[p] = trans[lane * TAGS + p];

        float fv = (lane == START_TAG) ? 0.f : -10000.0f;
        if (lane >= TAGS) fv = -1e30f;

        float feat = (lane < TAGS) ? sFeats[lane] : 0.f;   // prefetch t=0

        for (int t = 0; t < T_LEN; t++) {
            float featN = (lane < TAGS && t + 1 < T_LEN)
                        ? sFeats[(t + 1) * TAGS + lane] : 0.f;
            float f0 = __shfl_sync(0xffffffffu, fv, 0);
            float f1 = __shfl_sync(0xffffffffu, fv, 1);
            float f2 = __shfl_sync(0xffffffffu, fv, 2);
            float f3 = __shfl_sync(0xffffffffu, fv, 3);
            float f4 = __shfl_sync(0xffffffffu, fv, 4);
            float s0 = f0 + tr[0], s1 = f1 + tr[1], s2 = f2 + tr[2];
            float s3 = f3 + tr[3], s4 = f4 + tr[4];
            // branchless first-max tournament
            float m01 = fmaxf(s0, s1); int b01 = (s1 > s0) ? 1 : 0;
            float m23 = fmaxf(s2, s3); int b23 = (s3 > s2) ? 3 : 2;
            float m03 = fmaxf(m01, m23); int b03 = (m23 > m01) ? b23 : b01;
            float best = fmaxf(m03, s4); int bp = (s4 > m03) ? 4 : b03;
            if (lane < TAGS) {
                fv = best + feat;
                sBp[t * TAGS + lane] = (unsigned char)bp;
            }
            feat = featN;
        }

        float term = (lane < TAGS) ? (fv + trans[STOP_TAG * TAGS + lane]) : -1e30f;
        float t0 = __shfl_sync(0xffffffffu, term, 0);
        float t1 = __shfl_sync(0xffffffffu, term, 1);
        float t2 = __shfl_sync(0xffffffffu, term, 2);
        float t3 = __shfl_sync(0xffffffffu, term, 3);
        float t4 = __shfl_sync(0xffffffffu, term, 4);

        if (lane == 0) {
            float best = t0; int bl = 0;
            if (t1 > best) { best = t1; bl = 1; }
            if (t2 > best) { best = t2; bl = 2; }
            if (t3 > best) { best = t3; bl = 3; }
            if (t4 > best) { best = t4; bl = 4; }

            int base = (out_size > T_LEN) ? 1 : 0;
            if (base == 1 && out_size >= 1) out[0] = best;

            int y = bl;
            int idx = base + (T_LEN - 1);
            if (idx < out_size) out[idx] = (float)y;
            for (int t = T_LEN - 1; t >= 1; t--) {
                y = sBp[t * TAGS + y];
                idx = base + (t - 1);
                if (idx < out_size) out[idx] = (float)y;
            }
        }
    }
}

// ---------------- launcher ---------------------------------------------------
extern "C" void kernel_launch(void* const* d_in, const int* in_sizes, int n_in,
                              void* d_out, int out_size)
{
    const int*   sentence = (const int*)  d_in[0];
    const float* embed    = (const float*)d_in[1];
    const float* W_ih_f   = (const float*)d_in[2];
    const float* W_hh_f   = (const float*)d_in[3];
    const float* b_f      = (const float*)d_in[4];
    const float* W_ih_b   = (const float*)d_in[5];
    const float* W_hh_b   = (const float*)d_in[6];
    const float* b_b      = (const float*)d_in[7];
    const float* h0       = (const float*)d_in[8];
    const float* c0       = (const float*)d_in[9];
    const float* W_out    = (const float*)d_in[10];
    const float* b_out    = (const float*)d_in[11];
    const float* trans    = (const float*)d_in[12];
    float* out = (float*)d_out;

    setup_kernel<<<8192, 256>>>(h0);

    fused_kernel<<<RBLK + 1024, 256>>>(sentence, embed,
                                       W_ih_f, b_f, W_ih_b, b_b,
                                       W_hh_f, W_hh_b, c0);

    feats_kernel<<<T_LEN, TAGS * 32>>>(W_out, b_out);

    cudaFuncSetAttribute(viterbi_kernel,
                         cudaFuncAttributeMaxDynamicSharedMemorySize,
                         T_LEN * TAGS * sizeof(float));
    viterbi_kernel<<<1, 1024, T_LEN * TAGS * sizeof(float)>>>(trans, out, out_size);
}